// round 8
// baseline (speedup 1.0000x reference)
#include <cuda_runtime.h>
#include <cuda_bf16.h>
#include <cstdint>

// Problem constants (fixed by the reference setup_inputs)
constexpr int T_STEPS = 2048;
constexpr int BATCH   = 8192;
constexpr int CHUNK   = 32;                  // timesteps per pipeline stage
constexpr int NCHUNK  = T_STEPS / CHUNK;     // 64
constexpr int STAGES  = 3;                   // x staging ring depth
constexpr int EPB     = 32;                  // elements per block
constexpr int TPB     = 128;                 // w0:h0-poly w1:h1-poly w2:out-poly w3:producer

// Izhikevich params (regular spiking)
#define IZH_A   0.02f
#define IZH_B   0.2f
#define IZH_C   (-65.0f)
#define IZH_D   8.0f
#define IZH_VTH 30.0f

// ─── dynamic smem layout ───
// xring: STAGES*CHUNK*EPB float4              = 49152 B
// hbuf : 2 bufs * 2 neurons * CHUNK * EPB f32 = 16384 B
// zbuf : 2 bufs * 2 neurons * CHUNK/4 * EPB f4= 16384 B
// ybuf : 2 bufs * CHUNK/4 * EPB float4        =  8192 B
constexpr int XRING_B = STAGES * CHUNK * EPB * 16;
constexpr int HBUF_B  = 2 * 2 * CHUNK * EPB * 4;
constexpr int ZBUF_B  = 2 * 2 * (CHUNK / 4) * EPB * 16;
constexpr int YBUF_B  = 2 * (CHUNK / 4) * EPB * 16;
constexpr int SMEM_TOTAL = XRING_B + HBUF_B + ZBUF_B + YBUF_B;   // 90112

__device__ __forceinline__ void cp_async16(void* smem_dst, const void* gmem_src) {
    uint32_t s = (uint32_t)__cvta_generic_to_shared(smem_dst);
    asm volatile("cp.async.cg.shared.global [%0], [%1], 16;\n" :: "r"(s), "l"(gmem_src) : "memory");
}
__device__ __forceinline__ void cp_commit() {
    asm volatile("cp.async.commit_group;\n" ::: "memory");
}
__device__ __forceinline__ void cp_wait2() {
    asm volatile("cp.async.wait_group 2;\n" ::: "memory");
}

// ─── packed f32x2 helpers (sm_100+) ───
__device__ __forceinline__ uint64_t pk2(float lo, float hi) {
    uint64_t r; asm("mov.b64 %0, {%1, %2};" : "=l"(r) : "f"(lo), "f"(hi)); return r;
}
__device__ __forceinline__ void upk2(uint64_t v, float& lo, float& hi) {
    asm("mov.b64 {%0, %1}, %2;" : "=f"(lo), "=f"(hi) : "l"(v));
}
__device__ __forceinline__ uint64_t mul2(uint64_t a, uint64_t b) {
    uint64_t r; asm("mul.rn.f32x2 %0, %1, %2;" : "=l"(r) : "l"(a), "l"(b)); return r;
}
__device__ __forceinline__ uint64_t add2(uint64_t a, uint64_t b) {
    uint64_t r; asm("add.rn.f32x2 %0, %1, %2;" : "=l"(r) : "l"(a), "l"(b)); return r;
}
__device__ __forceinline__ uint64_t fma2(uint64_t a, uint64_t b, uint64_t c) {
    uint64_t r; asm("fma.rn.f32x2 %0, %1, %2, %3;" : "=l"(r) : "l"(a), "l"(b), "l"(c)); return r;
}

// Packed speculative Izhikevich step. State: vn (pre-reset v), up (u before +D), p (prev spike).
// Lane0 = no-spike path, lane1 = spike path; each lane is IEEE fp32 exact.
struct IzhState { float vn, up; bool p; };

__device__ __forceinline__ float izh_step_pk(IzhState& s, float I,
                                             uint64_t K004, uint64_t K5, uint64_t K140) {
    const float uB = s.up + IZH_D;                       // == fma(z=1, D, u')
    const uint64_t v2 = pk2(s.vn, IZH_C);
    const uint64_t u2 = pk2(s.up, uB);
    const uint64_t u2n = u2 ^ 0x8000000080000000ULL;     // exact negation of both lanes
    const uint64_t I2 = pk2(I, I);
    // poly(v,u,I) = v + ((0.04*v)*v + 5*v + 140 - u + I)  (one fma fusion: 5*v add)
    uint64_t t = mul2(K004, v2);
    t = mul2(t, v2);
    t = fma2(K5, v2, t);
    t = add2(t, K140);
    t = add2(t, u2n);
    t = add2(t, I2);
    t = add2(v2, t);
    float pA, pB; upk2(t, pA, pB);
    const float vnn  = s.p ? pB : pA;
    const float usel = s.p ? uB : s.up;
    s.up = usel + IZH_A * (IZH_B * vnn - usel);          // frozen order
    s.p  = (vnn >= IZH_VTH);
    s.vn = vnn;
    return s.p ? 1.0f : 0.0f;
}

__global__ __launch_bounds__(TPB) void snn_izh_4w_kernel(
    const float4* __restrict__ xs,     // [T, B] float4 (F_IN = 4)
    const float*  __restrict__ W_in,   // [2,4]
    const float*  __restrict__ b_in,   // [2]
    const float*  __restrict__ W_out,  // [1,2]
    const float*  __restrict__ b_out,  // [1]
    float*        __restrict__ out)    // [T, B]
{
    extern __shared__ char smem[];
    float4* xring = (float4*)smem;                                   // [STAGES][CHUNK][EPB]
    float*  hbuf  = (float*)(smem + XRING_B);                        // [2][2][CHUNK][EPB]
    float4* zbuf  = (float4*)(smem + XRING_B + HBUF_B);              // [2][2][CHUNK/4][EPB]
    float4* ybuf  = (float4*)(smem + XRING_B + HBUF_B + ZBUF_B);     // [2][CHUNK/4][EPB]

    const int wid  = threadIdx.x >> 5;
    const int lane = threadIdx.x & 31;
    const int elem = blockIdx.x * EPB + lane;

    const uint64_t K004 = pk2(0.04f, 0.04f);
    const uint64_t K5   = pk2(5.0f, 5.0f);
    const uint64_t K140 = pk2(140.0f, 140.0f);

    if (wid == 3) {
        // ───── PRODUCER: cp.async x (self-consumed), h-linears, y-linear ─────
        const float w00 = W_in[0], w01 = W_in[1], w02 = W_in[2], w03 = W_in[3];
        const float w10 = W_in[4], w11 = W_in[5], w12 = W_in[6], w13 = W_in[7];
        const float bi0 = b_in[0], bi1 = b_in[1];
        const float wo0 = W_out[0], wo1 = W_out[1];
        const float bo  = b_out[0];

        const float4* xp = xs + elem;

        // prologue: stages 0,1 (2 groups)
        #pragma unroll
        for (int s = 0; s < 2; s++) {
            #pragma unroll
            for (int k = 0; k < CHUNK; k++)
                cp_async16(&xring[(s * CHUNK + k) * EPB + lane],
                           xp + (size_t)(s * CHUNK + k) * BATCH);
            cp_commit();
        }

        #pragma unroll 1
        for (int c = 0; c <= NCHUNK + 2; c++) {
            // issue stage c+2 (or empty group), then wait for stage c
            const int ls = c + 2;
            if (ls < NCHUNK) {
                const int lslot = ls % STAGES;
                #pragma unroll
                for (int k = 0; k < CHUNK; k++)
                    cp_async16(&xring[(lslot * CHUNK + k) * EPB + lane],
                               xp + (size_t)(ls * CHUNK + k) * BATCH);
            }
            cp_commit();

            if (c < NCHUNK) {
                cp_wait2();                       // stage c complete (own copies)
                const int slot = c % STAGES;
                const int hb   = c & 1;
                #pragma unroll
                for (int k = 0; k < CHUNK; k++) {
                    const float4 x = xring[(slot * CHUNK + k) * EPB + lane];
                    const float h0 = w00 * x.x + w01 * x.y + w02 * x.z + w03 * x.w + bi0;
                    const float h1 = w10 * x.x + w11 * x.y + w12 * x.z + w13 * x.w + bi1;
                    hbuf[((hb * 2 + 0) * CHUNK + k) * EPB + lane] = h0;
                    hbuf[((hb * 2 + 1) * CHUNK + k) * EPB + lane] = h1;
                }
            }
            if (c >= 2 && c - 2 < NCHUNK) {
                const int zb = (c - 2) & 1;
                #pragma unroll
                for (int g = 0; g < CHUNK / 4; g++) {
                    const float4 z0q = zbuf[((zb * 2 + 0) * (CHUNK / 4) + g) * EPB + lane];
                    const float4 z1q = zbuf[((zb * 2 + 1) * (CHUNK / 4) + g) * EPB + lane];
                    float4 yq;
                    yq.x = z0q.x * wo0 + z1q.x * wo1 + bo;   // frozen order
                    yq.y = z0q.y * wo0 + z1q.y * wo1 + bo;
                    yq.z = z0q.z * wo0 + z1q.z * wo1 + bo;
                    yq.w = z0q.w * wo0 + z1q.w * wo1 + bo;
                    ybuf[(zb * (CHUNK / 4) + g) * EPB + lane] = yq;
                }
            }
            __syncthreads();
        }
    } else if (wid < 2) {
        // ───── HIDDEN poly warp (neuron n) ─────
        const int n = wid;
        IzhState st = { IZH_C, IZH_B * IZH_C, false };

        #pragma unroll 1
        for (int c = 0; c <= NCHUNK + 2; c++) {
            if (c >= 1 && c - 1 < NCHUNK) {
                const int hb = (c - 1) & 1;
                float4 zq;
                #pragma unroll
                for (int k = 0; k < CHUNK; k++) {
                    const float h = hbuf[((hb * 2 + n) * CHUNK + k) * EPB + lane];
                    const float z = izh_step_pk(st, h, K004, K5, K140);
                    if      ((k & 3) == 0) zq.x = z;
                    else if ((k & 3) == 1) zq.y = z;
                    else if ((k & 3) == 2) zq.z = z;
                    else { zq.w = z; zbuf[((hb * 2 + n) * (CHUNK / 4) + (k >> 2)) * EPB + lane] = zq; }
                }
            }
            __syncthreads();
        }
    } else {
        // ───── OUTPUT poly warp (lags 3 chunks behind x) ─────
        IzhState st = { IZH_C, IZH_B * IZH_C, false };
        float* op = out + elem;

        #pragma unroll 1
        for (int c = 0; c <= NCHUNK + 2; c++) {
            if (c >= 3 && c - 3 < NCHUNK) {
                const int yb    = (c - 3) & 1;
                const int tbase = (c - 3) * CHUNK;
                #pragma unroll
                for (int g = 0; g < CHUNK / 4; g++) {
                    const float4 yq = ybuf[(yb * (CHUNK / 4) + g) * EPB + lane];
                    #pragma unroll
                    for (int j = 0; j < 4; j++) {
                        const float y = (j == 0) ? yq.x : (j == 1) ? yq.y : (j == 2) ? yq.z : yq.w;
                        const float z2 = izh_step_pk(st, y, K004, K5, K140);
                        op[(size_t)(tbase + g * 4 + j) * BATCH] = z2;
                    }
                }
            }
            __syncthreads();
        }
    }
}

extern "C" void kernel_launch(void* const* d_in, const int* in_sizes, int n_in,
                              void* d_out, int out_size) {
    const float4* xs    = (const float4*)d_in[0];
    const float*  W_in  = (const float*)d_in[1];
    const float*  b_in  = (const float*)d_in[2];
    const float*  W_out = (const float*)d_in[3];
    const float*  b_out = (const float*)d_in[4];
    float* out = (float*)d_out;

    static bool attr_set = false;   // idempotent attribute set (host-side, not a stream op)
    if (!attr_set) {
        cudaFuncSetAttribute(snn_izh_4w_kernel,
                             cudaFuncAttributeMaxDynamicSharedMemorySize, SMEM_TOTAL);
        attr_set = true;
    }

    dim3 grid(BATCH / EPB);   // 256 blocks
    dim3 block(TPB);          // 4 warps: h0-poly / h1-poly / out-poly / producer
    snn_izh_4w_kernel<<<grid, block, SMEM_TOTAL>>>(xs, W_in, b_in, W_out, b_out, out);
}

// round 9
// speedup vs baseline: 1.0017x; 1.0017x over previous
#include <cuda_runtime.h>
#include <cuda_bf16.h>
#include <cstdint>

// Problem constants (fixed by the reference setup_inputs)
constexpr int T_STEPS = 2048;
constexpr int BATCH   = 8192;
constexpr int CHUNK   = 32;                  // timesteps per pipeline stage
constexpr int NCHUNK  = T_STEPS / CHUNK;     // 64
constexpr int STAGES  = 3;                   // x staging ring depth
constexpr int EPB     = 32;                  // elements per block
constexpr int TPB     = 128;                 // w0:h0-poly w1:h1-poly w2:out-poly w3:producer

// Izhikevich params (regular spiking)
#define IZH_A   0.02f
#define IZH_B   0.2f
#define IZH_C   (-65.0f)
#define IZH_D   8.0f
#define IZH_VTH 30.0f

// ─── dynamic smem layout ───
// xring: STAGES*CHUNK*EPB float4              = 49152 B
// hbuf : 2 bufs * 2 neurons * CHUNK * EPB f32 = 16384 B
// zbuf : 2 bufs * 2 neurons * CHUNK/4 * EPB f4= 16384 B
// ybuf : 2 bufs * CHUNK/4 * EPB float4        =  8192 B
constexpr int XRING_B = STAGES * CHUNK * EPB * 16;
constexpr int HBUF_B  = 2 * 2 * CHUNK * EPB * 4;
constexpr int ZBUF_B  = 2 * 2 * (CHUNK / 4) * EPB * 16;
constexpr int YBUF_B  = 2 * (CHUNK / 4) * EPB * 16;
constexpr int SMEM_TOTAL = XRING_B + HBUF_B + ZBUF_B + YBUF_B;   // 90112

__device__ __forceinline__ void cp_async16(void* smem_dst, const void* gmem_src) {
    uint32_t s = (uint32_t)__cvta_generic_to_shared(smem_dst);
    asm volatile("cp.async.cg.shared.global [%0], [%1], 16;\n" :: "r"(s), "l"(gmem_src) : "memory");
}
__device__ __forceinline__ void cp_commit() {
    asm volatile("cp.async.commit_group;\n" ::: "memory");
}
__device__ __forceinline__ void cp_wait2() {
    asm volatile("cp.async.wait_group 2;\n" ::: "memory");
}

// ─── packed f32x2 helpers (sm_100+) ───
__device__ __forceinline__ uint64_t pk2(float lo, float hi) {
    uint64_t r; asm("mov.b64 %0, {%1, %2};" : "=l"(r) : "f"(lo), "f"(hi)); return r;
}
__device__ __forceinline__ void upk2(uint64_t v, float& lo, float& hi) {
    asm("mov.b64 {%0, %1}, %2;" : "=f"(lo), "=f"(hi) : "l"(v));
}
__device__ __forceinline__ uint64_t mul2(uint64_t a, uint64_t b) {
    uint64_t r; asm("mul.rn.f32x2 %0, %1, %2;" : "=l"(r) : "l"(a), "l"(b)); return r;
}
__device__ __forceinline__ uint64_t add2(uint64_t a, uint64_t b) {
    uint64_t r; asm("add.rn.f32x2 %0, %1, %2;" : "=l"(r) : "l"(a), "l"(b)); return r;
}
__device__ __forceinline__ uint64_t fma2(uint64_t a, uint64_t b, uint64_t c) {
    uint64_t r; asm("fma.rn.f32x2 %0, %1, %2, %3;" : "=l"(r) : "l"(a), "l"(b), "l"(c)); return r;
}

// Packed speculative Izhikevich step. State: vn (pre-reset v), up (u before +D), p (prev spike).
// Lane0 = no-spike path, lane1 = spike path; each lane is IEEE fp32 exact.
struct IzhState { float vn, up; bool p; };

__device__ __forceinline__ float izh_step_pk(IzhState& s, float I,
                                             uint64_t K004, uint64_t K5, uint64_t K140) {
    const float uB = s.up + IZH_D;                       // == fma(z=1, D, u')
    const uint64_t v2 = pk2(s.vn, IZH_C);
    const uint64_t u2 = pk2(s.up, uB);
    const uint64_t u2n = u2 ^ 0x8000000080000000ULL;     // exact negation of both lanes
    const uint64_t I2 = pk2(I, I);
    // poly(v,u,I) = v + ((0.04*v)*v + 5*v + 140 - u + I)  (one fma fusion: 5*v add)
    uint64_t t = mul2(K004, v2);
    t = mul2(t, v2);
    t = fma2(K5, v2, t);
    t = add2(t, K140);
    t = add2(t, u2n);
    t = add2(t, I2);
    t = add2(v2, t);
    float pA, pB; upk2(t, pA, pB);
    const float vnn  = s.p ? pB : pA;
    const float usel = s.p ? uB : s.up;
    s.up = usel + IZH_A * (IZH_B * vnn - usel);          // frozen order
    s.p  = (vnn >= IZH_VTH);
    s.vn = vnn;
    return s.p ? 1.0f : 0.0f;
}

__global__ __launch_bounds__(TPB) void snn_izh_4w_kernel(
    const float4* __restrict__ xs,     // [T, B] float4 (F_IN = 4)
    const float*  __restrict__ W_in,   // [2,4]
    const float*  __restrict__ b_in,   // [2]
    const float*  __restrict__ W_out,  // [1,2]
    const float*  __restrict__ b_out,  // [1]
    float*        __restrict__ out)    // [T, B]
{
    extern __shared__ char smem[];
    float4* xring = (float4*)smem;                                   // [STAGES][CHUNK][EPB]
    float*  hbuf  = (float*)(smem + XRING_B);                        // [2][2][CHUNK][EPB]
    float4* zbuf  = (float4*)(smem + XRING_B + HBUF_B);              // [2][2][CHUNK/4][EPB]
    float4* ybuf  = (float4*)(smem + XRING_B + HBUF_B + ZBUF_B);     // [2][CHUNK/4][EPB]

    const int wid  = threadIdx.x >> 5;
    const int lane = threadIdx.x & 31;
    const int elem = blockIdx.x * EPB + lane;

    const uint64_t K004 = pk2(0.04f, 0.04f);
    const uint64_t K5   = pk2(5.0f, 5.0f);
    const uint64_t K140 = pk2(140.0f, 140.0f);

    if (wid == 3) {
        // ───── PRODUCER: cp.async x (self-consumed), h-linears, y-linear ─────
        const float w00 = W_in[0], w01 = W_in[1], w02 = W_in[2], w03 = W_in[3];
        const float w10 = W_in[4], w11 = W_in[5], w12 = W_in[6], w13 = W_in[7];
        const float bi0 = b_in[0], bi1 = b_in[1];
        const float wo0 = W_out[0], wo1 = W_out[1];
        const float bo  = b_out[0];

        const float4* xp = xs + elem;

        // prologue: stages 0,1 (2 groups)
        #pragma unroll
        for (int s = 0; s < 2; s++) {
            #pragma unroll
            for (int k = 0; k < CHUNK; k++)
                cp_async16(&xring[(s * CHUNK + k) * EPB + lane],
                           xp + (size_t)(s * CHUNK + k) * BATCH);
            cp_commit();
        }

        #pragma unroll 1
        for (int c = 0; c <= NCHUNK + 2; c++) {
            // issue stage c+2 (or empty group), then wait for stage c
            const int ls = c + 2;
            if (ls < NCHUNK) {
                const int lslot = ls % STAGES;
                #pragma unroll
                for (int k = 0; k < CHUNK; k++)
                    cp_async16(&xring[(lslot * CHUNK + k) * EPB + lane],
                               xp + (size_t)(ls * CHUNK + k) * BATCH);
            }
            cp_commit();

            if (c < NCHUNK) {
                cp_wait2();                       // stage c complete (own copies)
                const int slot = c % STAGES;
                const int hb   = c & 1;
                #pragma unroll
                for (int k = 0; k < CHUNK; k++) {
                    const float4 x = xring[(slot * CHUNK + k) * EPB + lane];
                    const float h0 = w00 * x.x + w01 * x.y + w02 * x.z + w03 * x.w + bi0;
                    const float h1 = w10 * x.x + w11 * x.y + w12 * x.z + w13 * x.w + bi1;
                    hbuf[((hb * 2 + 0) * CHUNK + k) * EPB + lane] = h0;
                    hbuf[((hb * 2 + 1) * CHUNK + k) * EPB + lane] = h1;
                }
            }
            if (c >= 2 && c - 2 < NCHUNK) {
                const int zb = (c - 2) & 1;
                #pragma unroll
                for (int g = 0; g < CHUNK / 4; g++) {
                    const float4 z0q = zbuf[((zb * 2 + 0) * (CHUNK / 4) + g) * EPB + lane];
                    const float4 z1q = zbuf[((zb * 2 + 1) * (CHUNK / 4) + g) * EPB + lane];
                    float4 yq;
                    yq.x = z0q.x * wo0 + z1q.x * wo1 + bo;   // frozen order
                    yq.y = z0q.y * wo0 + z1q.y * wo1 + bo;
                    yq.z = z0q.z * wo0 + z1q.z * wo1 + bo;
                    yq.w = z0q.w * wo0 + z1q.w * wo1 + bo;
                    ybuf[(zb * (CHUNK / 4) + g) * EPB + lane] = yq;
                }
            }
            __syncthreads();
        }
    } else if (wid < 2) {
        // ───── HIDDEN poly warp (neuron n) ─────
        const int n = wid;
        IzhState st = { IZH_C, IZH_B * IZH_C, false };

        #pragma unroll 1
        for (int c = 0; c <= NCHUNK + 2; c++) {
            if (c >= 1 && c - 1 < NCHUNK) {
                const int hb = (c - 1) & 1;
                float4 zq;
                #pragma unroll
                for (int k = 0; k < CHUNK; k++) {
                    const float h = hbuf[((hb * 2 + n) * CHUNK + k) * EPB + lane];
                    const float z = izh_step_pk(st, h, K004, K5, K140);
                    if      ((k & 3) == 0) zq.x = z;
                    else if ((k & 3) == 1) zq.y = z;
                    else if ((k & 3) == 2) zq.z = z;
                    else { zq.w = z; zbuf[((hb * 2 + n) * (CHUNK / 4) + (k >> 2)) * EPB + lane] = zq; }
                }
            }
            __syncthreads();
        }
    } else {
        // ───── OUTPUT poly warp (lags 3 chunks behind x) ─────
        IzhState st = { IZH_C, IZH_B * IZH_C, false };
        float* op = out + elem;

        #pragma unroll 1
        for (int c = 0; c <= NCHUNK + 2; c++) {
            if (c >= 3 && c - 3 < NCHUNK) {
                const int yb    = (c - 3) & 1;
                const int tbase = (c - 3) * CHUNK;
                #pragma unroll
                for (int g = 0; g < CHUNK / 4; g++) {
                    const float4 yq = ybuf[(yb * (CHUNK / 4) + g) * EPB + lane];
                    #pragma unroll
                    for (int j = 0; j < 4; j++) {
                        const float y = (j == 0) ? yq.x : (j == 1) ? yq.y : (j == 2) ? yq.z : yq.w;
                        const float z2 = izh_step_pk(st, y, K004, K5, K140);
                        op[(size_t)(tbase + g * 4 + j) * BATCH] = z2;
                    }
                }
            }
            __syncthreads();
        }
    }
}

extern "C" void kernel_launch(void* const* d_in, const int* in_sizes, int n_in,
                              void* d_out, int out_size) {
    const float4* xs    = (const float4*)d_in[0];
    const float*  W_in  = (const float*)d_in[1];
    const float*  b_in  = (const float*)d_in[2];
    const float*  W_out = (const float*)d_in[3];
    const float*  b_out = (const float*)d_in[4];
    float* out = (float*)d_out;

    static bool attr_set = false;   // idempotent attribute set (host-side, not a stream op)
    if (!attr_set) {
        cudaFuncSetAttribute(snn_izh_4w_kernel,
                             cudaFuncAttributeMaxDynamicSharedMemorySize, SMEM_TOTAL);
        attr_set = true;
    }

    dim3 grid(BATCH / EPB);   // 256 blocks
    dim3 block(TPB);          // 4 warps: h0-poly / h1-poly / out-poly / producer
    snn_izh_4w_kernel<<<grid, block, SMEM_TOTAL>>>(xs, W_in, b_in, W_out, b_out, out);
}